// round 11
// baseline (speedup 1.0000x reference)
#include <cuda_runtime.h>
#include <cstdint>

// Shapes fixed by the reference
#define NB   4
#define DB   8
#define CB   3
#define RB   4
#define KK   5
#define HH   128
#define WW   128
#define HWSZ (HH * WW)
#define TW   32
#define TH   4
#define SH_  (TH + 4)                 // 8
#define SW_  (TW + 4)                 // 36
#define TILE_FLOATS (CB * SH_ * SW_)  // 864

// i-row chunk: 20 planes (q = r*5+j) x 4 rows x 32 w
#define STAGE_FLOATS (20 * TH * TW)     // 2560
#define NUNITS       (STAGE_FLOATS / 4) // 640 x 16B cp.async units

__device__ __forceinline__ void cp16(uint32_t dst, const float* src) {
    asm volatile("cp.async.cg.shared.global [%0], [%1], 16;"
                 :: "r"(dst), "l"(src) : "memory");
}
__device__ __forceinline__ void cp_commit() {
    asm volatile("cp.async.commit_group;" ::: "memory");
}
__device__ __forceinline__ void cp_wait_all() {
    asm volatile("cp.async.wait_group 0;" ::: "memory");
}

// Block (32,2,4): tx = pixel col, si = r-group, tz = row. 256 threads, 8 CTAs/SM.
__global__ __launch_bounds__(256, 8)
void adaptive_conv_ps_v9(const float* __restrict__ burst,
                         const float* __restrict__ kernels,
                         float* __restrict__ out)
{
    __shared__ alignas(16) float smem[2 * STAGE_FLOATS + TILE_FLOATS];
    float* sb = smem + 2 * STAGE_FLOATS;          // burst tile [CB][SH_][SW_]
    const uint32_t smem_u32 = (uint32_t)__cvta_generic_to_shared(smem);

    const int nd = blockIdx.z;
    const int h0 = blockIdx.y * TH;
    const int w0 = blockIdx.x * TW;
    const int tx = threadIdx.x;                   // 0..31
    const int si = threadIdx.y;                   // 0..1
    const int tz = threadIdx.z;                   // 0..3
    const int tid = (tz * 2 + si) * 32 + tx;

    const float* kbase = kernels + (size_t)nd * (RB * KK * KK) * HWSZ;

    // ---- per-thread cp.async unit constants (unit u -> plane q, row, 16B seg) ----
    // u = q*32 + row*8 + seg ; plane q = r*5+j ; global plane g = r*25 + i*5 + j
    int goff[3];                                  // element offset, i-term excluded
    #pragma unroll
    for (int k = 0; k < 3; k++) {
        int u = tid + k * 256;
        int q   = u >> 5;
        int row = (u >> 3) & 3;
        int seg = u & 7;
        int r = q / 5, j = q - 5 * r;
        goff[k] = (r * 25 + j) * HWSZ + (h0 + row) * WW + w0 + seg * 4;
    }
    const bool has3 = (tid < NUNITS - 512);       // tid < 128

    // ---- prologue: issue chunk 0 into stage 0 ----
    {
        const uint32_t stg = smem_u32;
        cp16(stg + tid * 16,         kbase + goff[0]);
        cp16(stg + (tid + 256) * 16, kbase + goff[1]);
        if (has3)
            cp16(stg + (tid + 512) * 16, kbase + goff[2]);
        cp_commit();
    }

    // ---- stage burst tile (3 ch, halo 2, zero-pad OOB) ----
    const float* bptr = burst + (size_t)nd * CB * HWSZ;
    #pragma unroll
    for (int k = 0; k < 4; k++) {
        int idx = tid + k * 256;
        if (idx < TILE_FLOATS) {
            int c   = idx / (SH_ * SW_);
            int rem = idx - c * (SH_ * SW_);
            int sh  = rem / SW_;
            int sw  = rem - sh * SW_;
            int gh  = h0 + sh - 2;
            int gw  = w0 + sw - 2;
            float v = 0.0f;
            if (gh >= 0 && gh < HH && gw >= 0 && gw < WW)
                v = bptr[c * HWSZ + gh * WW + gw];
            sb[idx] = v;
        }
    }

    float a00 = 0.f, a01 = 0.f;
    float a10 = 0.f, a11 = 0.f;
    float a20 = 0.f, a21 = 0.f;

    // ---- single-sync pipeline: wait chunk i, sync, refill i+1, compute i ----
    #pragma unroll
    for (int i = 0; i < KK; i++) {
        cp_wait_all();                 // only chunk i is outstanding here
        __syncthreads();               // chunk i visible; stage (i+1)&1 is free

        if (i + 1 < KK) {              // refill freed stage with chunk i+1 (overlaps compute)
            const uint32_t stg = smem_u32 + ((i + 1) & 1) * (STAGE_FLOATS * 4);
            const int ioff = (i + 1) * (5 * HWSZ);
            cp16(stg + tid * 16,         kbase + goff[0] + ioff);
            cp16(stg + (tid + 256) * 16, kbase + goff[1] + ioff);
            if (has3)
                cp16(stg + (tid + 512) * 16, kbase + goff[2] + ioff);
            cp_commit();
        }

        const float* st = smem + (i & 1) * STAGE_FLOATS + (10 * si) * (TH * TW) + tz * TW + tx;
        const float* b0p = sb + (0 * SH_ + tz + i) * SW_ + tx;
        const float* b1p = sb + (1 * SH_ + tz + i) * SW_ + tx;
        const float* b2p = sb + (2 * SH_ + tz + i) * SW_ + tx;
        #pragma unroll
        for (int j = 0; j < KK; j++) {
            const float k0 = st[j * (TH * TW)];
            const float k1 = st[(5 + j) * (TH * TW)];
            const float b0 = b0p[j];
            const float b1 = b1p[j];
            const float b2 = b2p[j];
            a00 = fmaf(k0, b0, a00);  a01 = fmaf(k1, b0, a01);
            a10 = fmaf(k0, b1, a10);  a11 = fmaf(k1, b1, a11);
            a20 = fmaf(k0, b2, a20);  a21 = fmaf(k1, b2, a21);
        }
    }

    // ---- fused pixel shuffle: out (nd, c, 2H, 2W); row 2h+si, cols 2w..2w+1 ----
    const int h = h0 + tz;
    const int w = w0 + tx;
    float2* o2 = reinterpret_cast<float2*>(out);
    const size_t rowbase = ((size_t)nd * CB) * (2 * HH) + (2 * h + si);
    __stcs(&o2[(rowbase + 0 * 2 * HH) * WW + w], make_float2(a00, a01));
    __stcs(&o2[(rowbase + 1 * 2 * HH) * WW + w], make_float2(a10, a11));
    __stcs(&o2[(rowbase + 2 * 2 * HH) * WW + w], make_float2(a20, a21));
}

extern "C" void kernel_launch(void* const* d_in, const int* in_sizes, int n_in,
                              void* d_out, int out_size)
{
    const float* burst   = (const float*)d_in[0];   // (4,8,3,128,128)
    const float* kernels = (const float*)d_in[1];   // (4,8,4,5,5,128,128)
    float* out = (float*)d_out;                     // (4,8,3,256,256)

    dim3 block(32, 2, 4);                           // 256 threads
    dim3 grid(WW / TW, HH / TH, NB * DB);           // (4, 32, 32) = 4096 blocks
    adaptive_conv_ps_v9<<<grid, block>>>(burst, kernels, out);
}

// round 12
// speedup vs baseline: 1.1975x; 1.1975x over previous
#include <cuda_runtime.h>
#include <cstdint>

// Shapes fixed by the reference
#define NB   4
#define DB   8
#define CB   3
#define RB   4
#define KK   5
#define HH   128
#define WW   128
#define HWSZ (HH * WW)
#define TW   32
#define TH   4
#define SH_  (TH + 4)                 // 8
#define SW_  (TW + 4)                 // 36
#define TILE_FLOATS (CB * SH_ * SW_)  // 864

// i-row chunk: 20 planes (q = r*5+j) x 4 rows x 32 w
#define STAGE_FLOATS (20 * TH * TW)     // 2560 (10 KB)
#define NSTG 3
#define NUNITS (STAGE_FLOATS / 4)       // 640 x 16B cp.async units

__device__ __forceinline__ void cp16(uint32_t dst, const float* src) {
    asm volatile("cp.async.cg.shared.global [%0], [%1], 16;"
                 :: "r"(dst), "l"(src) : "memory");
}
__device__ __forceinline__ void cp_commit() {
    asm volatile("cp.async.commit_group;" ::: "memory");
}
__device__ __forceinline__ void cp_wait1() {
    asm volatile("cp.async.wait_group 1;" ::: "memory");
}

// Block (32,2,4): tx = pixel col, si = r-group, tz = row. 256 threads, 6 CTAs/SM.
__global__ __launch_bounds__(256, 6)
void adaptive_conv_ps_v10(const float* __restrict__ burst,
                          const float* __restrict__ kernels,
                          float* __restrict__ out)
{
    __shared__ alignas(16) float smem[NSTG * STAGE_FLOATS + TILE_FLOATS];
    float* sb = smem + NSTG * STAGE_FLOATS;       // burst tile [CB][SH_][SW_]
    const uint32_t smem_u32 = (uint32_t)__cvta_generic_to_shared(smem);

    const int nd = blockIdx.z;
    const int h0 = blockIdx.y * TH;
    const int w0 = blockIdx.x * TW;
    const int tx = threadIdx.x;                   // 0..31
    const int si = threadIdx.y;                   // 0..1
    const int tz = threadIdx.z;                   // 0..3
    const int tid = (tz * 2 + si) * 32 + tx;

    const float* kbase = kernels + (size_t)nd * (RB * KK * KK) * HWSZ;

    // ---- per-thread cp.async unit constants (unit u -> plane q, row, 16B seg) ----
    // u = q*32 + row*8 + seg ; plane q = r*5+j ; global plane = r*25 + i*5 + j
    int goff[3];                                  // element offset, i-term excluded
    #pragma unroll
    for (int k = 0; k < 3; k++) {
        int u = tid + k * 256;
        int q   = u >> 5;
        int row = (u >> 3) & 3;
        int seg = u & 7;
        int r = q / 5, j = q - 5 * r;
        goff[k] = (r * 25 + j) * HWSZ + (h0 + row) * WW + w0 + seg * 4;
    }
    const bool has3 = (tid < NUNITS - 512);       // tid < 128

    // ---- prologue: issue chunks 0 and 1 into stages 0 and 1 ----
    #pragma unroll
    for (int c = 0; c < 2; c++) {
        const uint32_t stg = smem_u32 + c * (STAGE_FLOATS * 4);
        cp16(stg + tid * 16,         kbase + goff[0] + c * (5 * HWSZ));
        cp16(stg + (tid + 256) * 16, kbase + goff[1] + c * (5 * HWSZ));
        if (has3)
            cp16(stg + (tid + 512) * 16, kbase + goff[2] + c * (5 * HWSZ));
        cp_commit();
    }

    // ---- stage burst tile (3 ch, halo 2, zero-pad OOB) ----
    const float* bptr = burst + (size_t)nd * CB * HWSZ;
    #pragma unroll
    for (int k = 0; k < 4; k++) {
        int idx = tid + k * 256;
        if (idx < TILE_FLOATS) {
            int c   = idx / (SH_ * SW_);
            int rem = idx - c * (SH_ * SW_);
            int sh  = rem / SW_;
            int sw  = rem - sh * SW_;
            int gh  = h0 + sh - 2;
            int gw  = w0 + sw - 2;
            float v = 0.0f;
            if (gh >= 0 && gh < HH && gw >= 0 && gw < WW)
                v = bptr[c * HWSZ + gh * WW + gw];
            sb[idx] = v;
        }
    }

    float a00 = 0.f, a01 = 0.f;
    float a10 = 0.f, a11 = 0.f;
    float a20 = 0.f, a21 = 0.f;

    // ---- 3-stage, single-sync pipeline ----
    #pragma unroll
    for (int i = 0; i < KK; i++) {
        cp_wait1();                    // chunk i landed (chunk i+1 may still fly)
        __syncthreads();               // chunk i visible; stage (i+2)%3 free

        if (i + 2 < KK) {              // refill BEFORE compute: ~2 iters of lead time
            const int s = (i + 2) % NSTG;
            const uint32_t stg = smem_u32 + s * (STAGE_FLOATS * 4);
            const int ioff = (i + 2) * (5 * HWSZ);
            cp16(stg + tid * 16,         kbase + goff[0] + ioff);
            cp16(stg + (tid + 256) * 16, kbase + goff[1] + ioff);
            if (has3)
                cp16(stg + (tid + 512) * 16, kbase + goff[2] + ioff);
            cp_commit();
        } else {
            cp_commit();               // keep group count aligned for wait<1>
        }

        const float* st = smem + (i % NSTG) * STAGE_FLOATS
                        + (10 * si) * (TH * TW) + tz * TW + tx;
        const float* b0p = sb + (0 * SH_ + tz + i) * SW_ + tx;
        const float* b1p = sb + (1 * SH_ + tz + i) * SW_ + tx;
        const float* b2p = sb + (2 * SH_ + tz + i) * SW_ + tx;
        #pragma unroll
        for (int j = 0; j < KK; j++) {
            const float k0 = st[j * (TH * TW)];
            const float k1 = st[(5 + j) * (TH * TW)];
            const float b0 = b0p[j];
            const float b1 = b1p[j];
            const float b2 = b2p[j];
            a00 = fmaf(k0, b0, a00);  a01 = fmaf(k1, b0, a01);
            a10 = fmaf(k0, b1, a10);  a11 = fmaf(k1, b1, a11);
            a20 = fmaf(k0, b2, a20);  a21 = fmaf(k1, b2, a21);
        }
    }

    // ---- fused pixel shuffle: out (nd, c, 2H, 2W); row 2h+si, cols 2w..2w+1 ----
    const int h = h0 + tz;
    const int w = w0 + tx;
    float2* o2 = reinterpret_cast<float2*>(out);
    const size_t rowbase = ((size_t)nd * CB) * (2 * HH) + (2 * h + si);
    __stcs(&o2[(rowbase + 0 * 2 * HH) * WW + w], make_float2(a00, a01));
    __stcs(&o2[(rowbase + 1 * 2 * HH) * WW + w], make_float2(a10, a11));
    __stcs(&o2[(rowbase + 2 * 2 * HH) * WW + w], make_float2(a20, a21));
}

extern "C" void kernel_launch(void* const* d_in, const int* in_sizes, int n_in,
                              void* d_out, int out_size)
{
    const float* burst   = (const float*)d_in[0];   // (4,8,3,128,128)
    const float* kernels = (const float*)d_in[1];   // (4,8,4,5,5,128,128)
    float* out = (float*)d_out;                     // (4,8,3,256,256)

    dim3 block(32, 2, 4);                           // 256 threads
    dim3 grid(WW / TW, HH / TH, NB * DB);           // (4, 32, 32) = 4096 blocks
    adaptive_conv_ps_v10<<<grid, block>>>(burst, kernels, out);
}

// round 13
// speedup vs baseline: 1.1985x; 1.0008x over previous
#include <cuda_runtime.h>
#include <cstdint>

// Shapes fixed by the reference
#define NB   4
#define DB   8
#define CB   3
#define RB   4
#define KK   5
#define HH   128
#define WW   128
#define HWSZ (HH * WW)
#define TW   32
#define TH   4
#define SH_  (TH + 4)                 // 8
#define SW_  (TW + 4)                 // 36
#define TILE_FLOATS (CB * SH_ * SW_)  // 864

// Per-warp sub-chunk: 10 planes (this si-group's r-pair x 5 j) x 1 row x 32 w
#define SUB_FLOATS  320               // 1280 B
#define SUB_BYTES   1280
#define WARPS       8
#define STAGES_FLOATS (WARPS * 2 * SUB_FLOATS)   // 5120 floats = 20 KB

__device__ __forceinline__ void cp16(uint32_t dst, const float* src) {
    asm volatile("cp.async.cg.shared.global [%0], [%1], 16;"
                 :: "r"(dst), "l"(src) : "memory");
}
__device__ __forceinline__ void cp_commit() {
    asm volatile("cp.async.commit_group;" ::: "memory");
}
__device__ __forceinline__ void cp_wait1() {
    asm volatile("cp.async.wait_group 1;" ::: "memory");
}

// Block (32,2,4): tx = pixel col, si = r-group, tz = row. 256 thr, 8 CTAs/SM.
// Each warp (tz,si) owns a private 2-stage cp.async ring -> no block barriers
// in the main loop; warps drift to smooth DRAM request arrivals.
__global__ __launch_bounds__(256, 8)
void adaptive_conv_ps_v11(const float* __restrict__ burst,
                          const float* __restrict__ kernels,
                          float* __restrict__ out)
{
    __shared__ alignas(16) float smem[STAGES_FLOATS + TILE_FLOATS];
    float* sb = smem + STAGES_FLOATS;             // burst tile [CB][SH_][SW_]
    const uint32_t smem_u32 = (uint32_t)__cvta_generic_to_shared(smem);

    const int nd = blockIdx.z;
    const int h0 = blockIdx.y * TH;
    const int w0 = blockIdx.x * TW;
    const int tx = threadIdx.x;                   // 0..31
    const int si = threadIdx.y;                   // 0..1
    const int tz = threadIdx.z;                   // 0..3
    const int wid  = tz * 2 + si;                 // warp id 0..7
    const int tid  = wid * 32 + tx;
    const int lane = tx;

    const float* kbase = kernels + (size_t)nd * (RB * KK * KK) * HWSZ;
    const uint32_t wbase = smem_u32 + wid * (2 * SUB_BYTES);

    // ---- per-lane cp.async units for this warp's sub-chunk ----
    // unit v in [0,80): plane p = v>>3 (0..9), seg = v&7 (16B each)
    // p<5 -> r = 2si, j = p ; p>=5 -> r = 2si+1, j = p-5
    // lane handles v = lane, lane+32, and (lane<16) lane+64
    int   goff[3];                                // global float offsets (i-term excluded)
    int   soff[3];                                // byte offsets within a stage
    #pragma unroll
    for (int k = 0; k < 3; k++) {
        int v   = lane + k * 32;
        int p   = v >> 3;
        int seg = v & 7;
        int rr  = si * 2 + (p >= 5 ? 1 : 0);
        int jj  = p - (p >= 5 ? 5 : 0);
        goff[k] = (rr * 25 + jj) * HWSZ + (h0 + tz) * WW + w0 + seg * 4;
        soff[k] = p * 128 + seg * 16;
    }
    const bool has3 = (lane < 16);

    // ---- prologue: issue chunks 0 and 1 into this warp's two stages ----
    #pragma unroll
    for (int c = 0; c < 2; c++) {
        const uint32_t stg = wbase + c * SUB_BYTES;
        cp16(stg + soff[0], kbase + goff[0] + c * (5 * HWSZ));
        cp16(stg + soff[1], kbase + goff[1] + c * (5 * HWSZ));
        if (has3)
            cp16(stg + soff[2], kbase + goff[2] + c * (5 * HWSZ));
        cp_commit();
    }

    // ---- stage burst tile (3 ch, halo 2, zero-pad OOB) ----
    const float* bptr = burst + (size_t)nd * CB * HWSZ;
    #pragma unroll
    for (int k = 0; k < 4; k++) {
        int idx = tid + k * 256;
        if (idx < TILE_FLOATS) {
            int c   = idx / (SH_ * SW_);
            int rem = idx - c * (SH_ * SW_);
            int sh  = rem / SW_;
            int sw  = rem - sh * SW_;
            int gh  = h0 + sh - 2;
            int gw  = w0 + sw - 2;
            float v = 0.0f;
            if (gh >= 0 && gh < HH && gw >= 0 && gw < WW)
                v = bptr[c * HWSZ + gh * WW + gw];
            sb[idx] = v;
        }
    }
    __syncthreads();          // only block-wide sync: burst tile ready

    float a00 = 0.f, a01 = 0.f;
    float a10 = 0.f, a11 = 0.f;
    float a20 = 0.f, a21 = 0.f;

    // ---- warp-local pipeline: wait own chunk i, compute, refill i+2 ----
    #pragma unroll
    for (int i = 0; i < KK; i++) {
        cp_wait1();           // this lane's chunk-i units landed
        __syncwarp();         // publish to sibling lanes

        const float* st  = smem + wid * (2 * SUB_FLOATS) + (i & 1) * SUB_FLOATS + tx;
        const float* b0p = sb + (0 * SH_ + tz + i) * SW_ + tx;
        const float* b1p = sb + (1 * SH_ + tz + i) * SW_ + tx;
        const float* b2p = sb + (2 * SH_ + tz + i) * SW_ + tx;
        #pragma unroll
        for (int j = 0; j < KK; j++) {
            const float k0 = st[j * 32];
            const float k1 = st[(5 + j) * 32];
            const float b0 = b0p[j];
            const float b1 = b1p[j];
            const float b2 = b2p[j];
            a00 = fmaf(k0, b0, a00);  a01 = fmaf(k1, b0, a01);
            a10 = fmaf(k0, b1, a10);  a11 = fmaf(k1, b1, a11);
            a20 = fmaf(k0, b2, a20);  a21 = fmaf(k1, b2, a21);
        }

        __syncwarp();         // all lanes done reading stage i&1
        if (i + 2 < KK) {     // refill freed stage with chunk i+2
            const uint32_t stg = wbase + (i & 1) * SUB_BYTES;
            const int ioff = (i + 2) * (5 * HWSZ);
            cp16(stg + soff[0], kbase + goff[0] + ioff);
            cp16(stg + soff[1], kbase + goff[1] + ioff);
            if (has3)
                cp16(stg + soff[2], kbase + goff[2] + ioff);
            cp_commit();
        } else {
            cp_commit();      // empty group keeps wait<1> ledger aligned
        }
    }

    // ---- fused pixel shuffle: out (nd, c, 2H, 2W); row 2h+si, cols 2w..2w+1 ----
    const int h = h0 + tz;
    const int w = w0 + tx;
    float2* o2 = reinterpret_cast<float2*>(out);
    const size_t rowbase = ((size_t)nd * CB) * (2 * HH) + (2 * h + si);
    __stcs(&o2[(rowbase + 0 * 2 * HH) * WW + w], make_float2(a00, a01));
    __stcs(&o2[(rowbase + 1 * 2 * HH) * WW + w], make_float2(a10, a11));
    __stcs(&o2[(rowbase + 2 * 2 * HH) * WW + w], make_float2(a20, a21));
}

extern "C" void kernel_launch(void* const* d_in, const int* in_sizes, int n_in,
                              void* d_out, int out_size)
{
    const float* burst   = (const float*)d_in[0];   // (4,8,3,128,128)
    const float* kernels = (const float*)d_in[1];   // (4,8,4,5,5,128,128)
    float* out = (float*)d_out;                     // (4,8,3,256,256)

    dim3 block(32, 2, 4);                           // 256 threads
    dim3 grid(WW / TW, HH / TH, NB * DB);           // (4, 32, 32) = 4096 blocks
    adaptive_conv_ps_v11<<<grid, block>>>(burst, kernels, out);
}